// round 14
// baseline (speedup 1.0000x reference)
#include <cuda_runtime.h>
#include <cuda_fp16.h>
#include <math.h>
#include <stdint.h>

// ---------------------------------------------------------------------------
// TrigramAttention on GB300 (sm_103a), Round 13:
//   - GEMM: 3-stage cp.async pipeline (was 2) to hide the ~1.2Kcyc/chunk
//     load-wait bubble. Shape unchanged (128x128, 256thr, 2 CTAs/SM).
//   - Attention: 256 thr / 16 rows per block -> 16 warps/SM (was 12),
//     same conflict-free rotation; latency-bound kernel gets more cover.
// ---------------------------------------------------------------------------

#define C_EMBD   1024
#define T_LEN    4096
#define MAX_ROWS (8 * 4096)

#define NCHUNK   16                    // K=1024 / BK=64
#define A_TILE_B 16384                 // 128 rows x 128 bytes
#define B_TILE_B 16384
#define STAGE_B  (A_TILE_B + B_TILE_B)           // 32KB
#define NSTAGE   3
#define GEMM_SMEM (NSTAGE * STAGE_B)   // 96KB -> 2 CTAs/SM

#define AT_ROWS  16
#define AT_SMEM  ((16 + 18 + 18) * C_EMBD * 2)   // 106496 B -> 2 CTAs/SM

// ---------------- scratch (__device__ globals) ------------------------------
__device__ __half g_xh[(size_t)MAX_ROWS * C_EMBD];
__device__ __half g_yh[(size_t)MAX_ROWS * C_EMBD];
__device__ __half g_w[4][(size_t)C_EMBD * C_EMBD];   // Wq;Wk;Wv;Wo contiguous
__device__ __half g_q[(size_t)MAX_ROWS * C_EMBD];
__device__ __half g_k[(size_t)MAX_ROWS * C_EMBD];
__device__ __half g_v[(size_t)MAX_ROWS * C_EMBD];

// ---------------- helpers ---------------------------------------------------
__device__ __forceinline__ uint32_t smem_u32(const void* p) {
    uint32_t a;
    asm("{ .reg .u64 t; cvta.to.shared.u64 t, %1; cvt.u32.u64 %0, t; }"
        : "=r"(a) : "l"(p));
    return a;
}
__device__ __forceinline__ void cp16(uint32_t dst, const void* src) {
    asm volatile("cp.async.cg.shared.global [%0], [%1], 16;"
                 :: "r"(dst), "l"(src) : "memory");
}
__device__ __forceinline__ uint32_t swz128(uint32_t off) {
    return off ^ ((off >> 3) & 0x70);
}
__device__ __forceinline__ void ldsm4(uint32_t* r, uint32_t addr) {
    asm volatile("ldmatrix.sync.aligned.m8n8.x4.shared.b16 {%0,%1,%2,%3}, [%4];"
                 : "=r"(r[0]), "=r"(r[1]), "=r"(r[2]), "=r"(r[3]) : "r"(addr));
}
__device__ __forceinline__ void mma16816(float* d, const uint32_t* a,
                                         uint32_t b0, uint32_t b1) {
    asm volatile(
        "mma.sync.aligned.m16n8k16.row.col.f32.f16.f16.f32 "
        "{%0,%1,%2,%3}, {%4,%5,%6,%7}, {%8,%9}, {%0,%1,%2,%3};"
        : "+f"(d[0]), "+f"(d[1]), "+f"(d[2]), "+f"(d[3])
        : "r"(a[0]), "r"(a[1]), "r"(a[2]), "r"(a[3]), "r"(b0), "r"(b1));
}
__device__ __forceinline__ uint32_t ldsm_addr(uint32_t tile, int rowBase,
                                              int kk, int lane) {
    int row   = rowBase + (lane & 15);
    int chunk = kk * 2 + (lane >> 4);
    return tile + (uint32_t)(row * 128 + ((chunk ^ (row & 7)) << 4));
}
__device__ __forceinline__ void store2(float* p, float a, float b) {
    float2 v = {a, b}; *(float2*)p = v;
}
__device__ __forceinline__ void store2(__half* p, float a, float b) {
    *(__half2*)p = __floats2half2_rn(a, b);
}
__device__ __forceinline__ void dot8(float& pa, float& pb, uint4 a, uint4 b) {
    const __half2* ah = (const __half2*)&a;
    const __half2* bh = (const __half2*)&b;
#pragma unroll
    for (int i = 0; i < 4; i++) {
        float2 x = __half22float2(ah[i]);
        float2 y = __half22float2(bh[i]);
        pa = fmaf(x.x, y.x, pa);
        pb = fmaf(x.y, y.y, pb);
    }
}

// ---------------------------------------------------------------------------
// GemmCore: 3-stage cp.async pipeline; precomputed swizzled offsets;
// global pointers advance +128B per chunk. 256 thr, 8 warps 2(m)x4(n).
// ---------------------------------------------------------------------------
struct GemmCore {
    uint32_t sb;
    int tid, wid, lane, wm, wn;
    uint32_t soA[4], soB[4];
    const char *gA[4], *gB[4];

    __device__ __forceinline__ void init(uint32_t sb_, int tid_,
                                         const char* pA, const char* pB) {
        sb = sb_; tid = tid_;
        wid = tid >> 5; lane = tid & 31;
        wm = wid & 1; wn = wid >> 1;
#pragma unroll
        for (int u = 0; u < 4; ++u) {
            const int v   = tid + 256 * u;
            const int row = v >> 3;
            const int c16 = v & 7;
            const uint32_t off = swz128((uint32_t)(row * 128 + c16 * 16));
            soA[u] = off; soB[u] = off;
            gA[u] = pA + (size_t)row * 2048 + c16 * 16;
            gB[u] = pB + (size_t)row * 2048 + c16 * 16;
        }
    }
    __device__ __forceinline__ void load_stage(int s) {
        const uint32_t st = sb + s * STAGE_B;
#pragma unroll
        for (int u = 0; u < 4; ++u) cp16(st + soA[u], gA[u]);
#pragma unroll
        for (int u = 0; u < 4; ++u) cp16(st + A_TILE_B + soB[u], gB[u]);
        asm volatile("cp.async.commit_group;" ::: "memory");
#pragma unroll
        for (int u = 0; u < 4; ++u) { gA[u] += 128; gB[u] += 128; }
    }
    __device__ __forceinline__ void mainloop(float acc[4][4][4]) {
        load_stage(0);
        load_stage(1);
        int s = 0;                       // stage of chunk i
        for (int i = 0; i < NCHUNK; ++i) {
            if (i + 2 < NCHUNK) {
                int s2 = s + 2; if (s2 >= NSTAGE) s2 -= NSTAGE;
                load_stage(s2);
                asm volatile("cp.async.wait_group 2;" ::: "memory");
            } else if (i + 2 == NCHUNK) {
                asm volatile("cp.async.wait_group 1;" ::: "memory");
            } else {
                asm volatile("cp.async.wait_group 0;" ::: "memory");
            }
            __syncthreads();
            const uint32_t st = sb + s * STAGE_B;
            const uint32_t tA = st;
            const uint32_t tB = st + A_TILE_B;
#pragma unroll
            for (int kk = 0; kk < 4; ++kk) {
                uint32_t a[4][4], b[2][4];
#pragma unroll
                for (int mt = 0; mt < 4; mt++)
                    ldsm4(a[mt], ldsm_addr(tA, wm * 64 + mt * 16, kk, lane));
#pragma unroll
                for (int p = 0; p < 2; p++)
                    ldsm4(b[p], ldsm_addr(tB, wn * 32 + p * 16, kk, lane));
#pragma unroll
                for (int mt = 0; mt < 4; mt++)
#pragma unroll
                    for (int nt = 0; nt < 4; nt++)
                        mma16816(acc[mt][nt], a[mt],
                                 b[nt >> 1][nt & 1], b[nt >> 1][(nt & 1) + 2]);
            }
            __syncthreads();
            if (++s == NSTAGE) s = 0;
        }
    }
};

// ---------------------------------------------------------------------------
// Fused QKV GEMM: W = [Wq;Wk;Wv] (3072x1024), seg = bn>>10.
// ---------------------------------------------------------------------------
__global__ __launch_bounds__(256, 2)
void gemm_qkv(const __half* __restrict__ A,
              const __half* __restrict__ W,
              const float* __restrict__ bq, const float* __restrict__ bk,
              const float* __restrict__ bv,
              __half* __restrict__ q, __half* __restrict__ k,
              __half* __restrict__ v)
{
    extern __shared__ char smem[];
    const int bn = blockIdx.x * 128;
    const int bm = blockIdx.y * 128;
    const int seg = bn >> 10;
    const int ncol = bn & 1023;

    const float* bias = (seg == 0) ? bq : (seg == 1) ? bk : bv;
    __half* out       = (seg == 0) ? q  : (seg == 1) ? k  : v;

    GemmCore core;
    core.init(smem_u32(smem), threadIdx.x,
              (const char*)A + (size_t)bm * 2048,
              (const char*)W + (size_t)bn * 2048);

    float acc[4][4][4];
#pragma unroll
    for (int mt = 0; mt < 4; mt++)
#pragma unroll
        for (int nt = 0; nt < 4; nt++)
#pragma unroll
            for (int r = 0; r < 4; r++) acc[mt][nt][r] = 0.0f;

    core.mainloop(acc);

    const int g = core.lane >> 2;
    const int t = core.lane & 3;
#pragma unroll
    for (int nt = 0; nt < 4; nt++) {
        const int col = ncol + core.wn * 32 + nt * 8 + 2 * t;
        const float b0 = bias[col], b1 = bias[col + 1];
#pragma unroll
        for (int mt = 0; mt < 4; mt++) {
            const int row0 = bm + core.wm * 64 + mt * 16 + g;
            store2(out + (size_t)row0 * C_EMBD + col,
                   acc[mt][nt][0] + b0, acc[mt][nt][1] + b1);
            store2(out + (size_t)(row0 + 8) * C_EMBD + col,
                   acc[mt][nt][2] + b0, acc[mt][nt][3] + b1);
        }
    }
}

// ---------------------------------------------------------------------------
__global__ __launch_bounds__(256, 2)
void gemm_out(const __half* __restrict__ A,
              const __half* __restrict__ W,
              const float* __restrict__ bias,
              float* __restrict__ Cout)
{
    extern __shared__ char smem[];
    const int bn = blockIdx.x * 128;
    const int bm = blockIdx.y * 128;

    GemmCore core;
    core.init(smem_u32(smem), threadIdx.x,
              (const char*)A + (size_t)bm * 2048,
              (const char*)W + (size_t)bn * 2048);

    float acc[4][4][4];
#pragma unroll
    for (int mt = 0; mt < 4; mt++)
#pragma unroll
        for (int nt = 0; nt < 4; nt++)
#pragma unroll
            for (int r = 0; r < 4; r++) acc[mt][nt][r] = 0.0f;

    core.mainloop(acc);

    const int g = core.lane >> 2;
    const int t = core.lane & 3;
#pragma unroll
    for (int nt = 0; nt < 4; nt++) {
        const int col = bn + core.wn * 32 + nt * 8 + 2 * t;
        const float b0 = bias[col], b1 = bias[col + 1];
#pragma unroll
        for (int mt = 0; mt < 4; mt++) {
            const int row0 = bm + core.wm * 64 + mt * 16 + g;
            store2(Cout + (size_t)row0 * C_EMBD + col,
                   acc[mt][nt][0] + b0, acc[mt][nt][1] + b1);
            store2(Cout + (size_t)(row0 + 8) * C_EMBD + col,
                   acc[mt][nt][2] + b0, acc[mt][nt][3] + b1);
        }
    }
}

// ---------------------------------------------------------------------------
__global__ __launch_bounds__(256)
void conv_fp16(const float* __restrict__ in, __half* __restrict__ out, int n4)
{
    int i = blockIdx.x * 256 + threadIdx.x;
    if (i >= n4) return;
    float4 x = ((const float4*)in)[i];
    __half h[4] = {__float2half(x.x), __float2half(x.y),
                   __float2half(x.z), __float2half(x.w)};
    ((ushort4*)out)[i] = *(ushort4*)h;
}

__global__ __launch_bounds__(256)
void conv_w4(const float* __restrict__ w0, const float* __restrict__ w1,
             const float* __restrict__ w2, const float* __restrict__ w3,
             __half* __restrict__ out, int n4each)
{
    int i = blockIdx.x * 256 + threadIdx.x;
    int which = i / n4each;
    int idx   = i - which * n4each;
    if (which >= 4) return;
    const float* src = (which == 0) ? w0 : (which == 1) ? w1
                     : (which == 2) ? w2 : w3;
    float4 x = ((const float4*)src)[idx];
    __half h[4] = {__float2half(x.x), __float2half(x.y),
                   __float2half(x.z), __float2half(x.w)};
    ((ushort4*)(out))[(size_t)which * n4each + idx] = *(ushort4*)h;
}

// ---------------------------------------------------------------------------
// Banded trigram attention, thread-per-(row,head).
// Block: 256 threads = 16 rows x 16 heads. SMEM: q[16], k[18], v[18] rows
// (2-row halo, clamped; validity via t>=j). (i+h)&7 rotation keeps LDS
// conflict-free (each 8-lane phase hits distinct 16B bank groups).
// ---------------------------------------------------------------------------
__global__ __launch_bounds__(256, 2)
void trigram_attn(const __half* __restrict__ q, const __half* __restrict__ k,
                  const __half* __restrict__ v, __half* __restrict__ y)
{
    extern __shared__ __half sm[];
    __half* smq = sm;                        // 16 * 1024
    __half* smk = sm + 16 * C_EMBD;          // 18 * 1024
    __half* smv = smk + 18 * C_EMBD;         // 18 * 1024

    const int tid = threadIdx.x;
    const int r0  = blockIdx.x * AT_ROWS;

    // stage q: 16 rows * 128 uint4 = 2048 uint4
    {
        const uint4* src = (const uint4*)(q + (size_t)r0 * C_EMBD);
        uint4* dst = (uint4*)smq;
#pragma unroll
        for (int u = 0; u < 8; u++) dst[tid + 256 * u] = src[tid + 256 * u];
    }
    // stage k, v: 18 rows * 128 uint4 = 2304 uint4 each (rows r0-2..r0+15)
    {
        const uint4* ks = (const uint4*)k;
        const uint4* vs = (const uint4*)v;
        uint4* kd = (uint4*)smk;
        uint4* vd = (uint4*)smv;
#pragma unroll
        for (int u = 0; u < 9; u++) {
            int idx = tid + 256 * u;            // 0..2303
            int rr  = idx >> 7;                 // 0..17
            int cc  = idx & 127;
            int gr  = r0 - 2 + rr; if (gr < 0) gr = 0;
            kd[idx] = ks[(size_t)gr * 128 + cc];
            vd[idx] = vs[(size_t)gr * 128 + cc];
        }
    }
    __syncthreads();

    const int lr = tid >> 4;                   // 0..15
    const int h  = tid & 15;
    const int t  = (r0 & (T_LEN - 1)) + lr;

    const uint4* qrow = (const uint4*)(smq + lr * C_EMBD + h * 64);
    const uint4* k0   = (const uint4*)(smk + (lr + 2) * C_EMBD + h * 64);
    const uint4* k1   = (const uint4*)(smk + (lr + 1) * C_EMBD + h * 64);
    const uint4* k2   = (const uint4*)(smk + (lr + 0) * C_EMBD + h * 64);

    float p0a = 0, p0b = 0, p1a = 0, p1b = 0, p2a = 0, p2b = 0;
#pragma unroll
    for (int i = 0; i < 8; i++) {
        const int c = (i + h) & 7;
        const uint4 qc = qrow[c];
        dot8(p0a, p0b, qc, k0[c]);
        dot8(p1a, p1b, qc, k1[c]);
        dot8(p2a, p2b, qc, k2[c]);
    }
    float s0 = (p0a + p0b) * 0.125f;
    float s1 = (p1a + p1b) * 0.125f;
    float s2 = (p2a + p2b) * 0.125f;

    float m = s0;
    if (t >= 1 && s1 > m) m = s1;
    if (t >= 2 && s2 > m) m = s2;
    float e0 = expf(s0 - m);
    float e1 = (t >= 1) ? expf(s1 - m) : 0.0f;
    float e2 = (t >= 2) ? expf(s2 - m) : 0.0f;
    const float inv = 1.0f / (e0 + e1 + e2);
    const float a0 = e0 * inv, a1 = e1 * inv, a2 = e2 * inv;

    const uint4* v0 = (const uint4*)(smv + (lr + 2) * C_EMBD + h * 64);
    const uint4* v1 = (const uint4*)(smv + (lr + 1) * C_EMBD + h * 64);
    const uint4* v2 = (const uint4*)(smv + (lr + 0) * C_EMBD + h * 64);
    uint4* yout = (uint4*)(y + (size_t)(r0 + lr) * C_EMBD + h * 64);

#pragma unroll
    for (int i = 0; i < 8; i++) {
        const int c = (i + h) & 7;
        const uint4 w0 = v0[c], w1 = v1[c], w2 = v2[c];
        const __half2* h0 = (const __half2*)&w0;
        const __half2* h1 = (const __half2*)&w1;
        const __half2* h2 = (const __half2*)&w2;
        uint4 o;
        __half2* oh = (__half2*)&o;
#pragma unroll
        for (int e = 0; e < 4; e++) {
            float2 f0 = __half22float2(h0[e]);
            float2 f1 = __half22float2(h1[e]);
            float2 f2 = __half22float2(h2[e]);
            float yx = a0 * f0.x + a1 * f1.x + a2 * f2.x;
            float yy = a0 * f0.y + a1 * f1.y + a2 * f2.y;
            oh[e] = __floats2half2_rn(yx, yy);
        }
        yout[c] = o;
    }
}

// ---------------------------------------------------------------------------
extern "C" void kernel_launch(void* const* d_in, const int* in_sizes, int n_in,
                              void* d_out, int out_size)
{
    const float* x  = (const float*)d_in[0];
    const float* W[4]    = {(const float*)d_in[1], (const float*)d_in[3],
                            (const float*)d_in[5], (const float*)d_in[7]};
    const float* bias[4] = {(const float*)d_in[2], (const float*)d_in[4],
                            (const float*)d_in[6], (const float*)d_in[8]};
    float* out = (float*)d_out;

    const int rows = in_sizes[0] / C_EMBD;   // 32768

    __half *xh, *yh, *w, *q, *k, *v;
    cudaGetSymbolAddress((void**)&xh, g_xh);
    cudaGetSymbolAddress((void**)&yh, g_yh);
    cudaGetSymbolAddress((void**)&w,  g_w);
    cudaGetSymbolAddress((void**)&q,  g_q);
    cudaGetSymbolAddress((void**)&k,  g_k);
    cudaGetSymbolAddress((void**)&v,  g_v);

    cudaFuncSetAttribute(gemm_qkv,
                         cudaFuncAttributeMaxDynamicSharedMemorySize, GEMM_SMEM);
    cudaFuncSetAttribute(gemm_out,
                         cudaFuncAttributeMaxDynamicSharedMemorySize, GEMM_SMEM);
    cudaFuncSetAttribute(trigram_attn,
                         cudaFuncAttributeMaxDynamicSharedMemorySize, AT_SMEM);

    const int xn4 = rows * C_EMBD / 4;
    conv_fp16<<<(xn4 + 255) / 256, 256>>>(x, xh, xn4);
    const int wn4 = C_EMBD * C_EMBD / 4;
    conv_w4<<<(4 * wn4 + 255) / 256, 256>>>(W[0], W[1], W[2], W[3], w, wn4);

    const size_t WSZ = (size_t)C_EMBD * C_EMBD;

    dim3 gqkv(3 * C_EMBD / 128, rows / 128);
    gemm_qkv<<<gqkv, 256, GEMM_SMEM>>>(xh, w, bias[0], bias[1], bias[2],
                                       q, k, v);

    trigram_attn<<<rows / AT_ROWS, 256, AT_SMEM>>>(q, k, v, yh);

    dim3 gout(C_EMBD / 128, rows / 128);
    gemm_out<<<gout, 256, GEMM_SMEM>>>(yh, w + 3 * WSZ, bias[3], out);
}

// round 16
// speedup vs baseline: 1.0190x; 1.0190x over previous
#include <cuda_runtime.h>
#include <cuda_fp16.h>
#include <math.h>
#include <stdint.h>

// ---------------------------------------------------------------------------
// TrigramAttention on GB300 (sm_103a), Round 15 (= R14 resubmitted after
// infra failure — container died before any measurement):
//   - GEMM: slim addressing (single base ptr + u*const; soA==soB, so[u]=
//     so+4096u) frees ~28 regs; spend them on explicit fragment double-
//     buffering (ldsm kk+1 before mma kk) to hide the ~29cyc LDS latency
//     that holds tensor at 58%. 2-stage cp.async (3-stage was neutral).
//   - Attention: no q staging (single consumer); k/v SMEM 40KB, 4 CTAs/SM.
//   - Convs merged into one launch.
// ---------------------------------------------------------------------------

#define C_EMBD   1024
#define T_LEN    4096
#define MAX_ROWS (8 * 4096)

#define NCHUNK   16                    // K=1024 / BK=64
#define A_TILE_B 16384                 // 128 rows x 128 bytes
#define B_TILE_B 16384
#define STAGE_B  (A_TILE_B + B_TILE_B)           // 32KB
#define GEMM_SMEM (2 * STAGE_B)        // 64KB -> 2 CTAs/SM

#define AT_ROWS  8
#define AT_SMEM  ((10 + 10) * C_EMBD * 2)        // k+v = 40KB -> 4 CTAs/SM

// ---------------- scratch (__device__ globals) ------------------------------
__device__ __half g_xh[(size_t)MAX_ROWS * C_EMBD];
__device__ __half g_yh[(size_t)MAX_ROWS * C_EMBD];
__device__ __half g_w[4][(size_t)C_EMBD * C_EMBD];   // Wq;Wk;Wv;Wo contiguous
__device__ __half g_q[(size_t)MAX_ROWS * C_EMBD];
__device__ __half g_k[(size_t)MAX_ROWS * C_EMBD];
__device__ __half g_v[(size_t)MAX_ROWS * C_EMBD];

// ---------------- helpers ---------------------------------------------------
__device__ __forceinline__ uint32_t smem_u32(const void* p) {
    uint32_t a;
    asm("{ .reg .u64 t; cvta.to.shared.u64 t, %1; cvt.u32.u64 %0, t; }"
        : "=r"(a) : "l"(p));
    return a;
}
__device__ __forceinline__ void cp16(uint32_t dst, const void* src) {
    asm volatile("cp.async.cg.shared.global [%0], [%1], 16;"
                 :: "r"(dst), "l"(src) : "memory");
}
__device__ __forceinline__ uint32_t swz128(uint32_t off) {
    return off ^ ((off >> 3) & 0x70);
}
__device__ __forceinline__ void ldsm4(uint32_t* r, uint32_t addr) {
    asm volatile("ldmatrix.sync.aligned.m8n8.x4.shared.b16 {%0,%1,%2,%3}, [%4];"
                 : "=r"(r[0]), "=r"(r[1]), "=r"(r[2]), "=r"(r[3]) : "r"(addr));
}
__device__ __forceinline__ void mma16816(float* d, const uint32_t* a,
                                         uint32_t b0, uint32_t b1) {
    asm volatile(
        "mma.sync.aligned.m16n8k16.row.col.f32.f16.f16.f32 "
        "{%0,%1,%2,%3}, {%4,%5,%6,%7}, {%8,%9}, {%0,%1,%2,%3};"
        : "+f"(d[0]), "+f"(d[1]), "+f"(d[2]), "+f"(d[3])
        : "r"(a[0]), "r"(a[1]), "r"(a[2]), "r"(a[3]), "r"(b0), "r"(b1));
}
__device__ __forceinline__ uint32_t ldsm_addr(uint32_t tile, int rowBase,
                                              int kk, int lane) {
    int row   = rowBase + (lane & 15);
    int chunk = kk * 2 + (lane >> 4);
    return tile + (uint32_t)(row * 128 + ((chunk ^ (row & 7)) << 4));
}
__device__ __forceinline__ void store2(float* p, float a, float b) {
    float2 v = {a, b}; *(float2*)p = v;
}
__device__ __forceinline__ void store2(__half* p, float a, float b) {
    *(__half2*)p = __floats2half2_rn(a, b);
}
__device__ __forceinline__ void dot8(float& pa, float& pb, uint4 a, uint4 b) {
    const __half2* ah = (const __half2*)&a;
    const __half2* bh = (const __half2*)&b;
#pragma unroll
    for (int i = 0; i < 4; i++) {
        float2 x = __half22float2(ah[i]);
        float2 y = __half22float2(bh[i]);
        pa = fmaf(x.x, y.x, pa);
        pb = fmaf(x.y, y.y, pb);
    }
}

// ---------------------------------------------------------------------------
// GemmCore v2: slim addressing (1 ptr per operand, one swizzled offset) +
// fragment double-buffering. 256 thr, 8 warps 2(m)x4(n), warp tile 64x32,
// 2-stage cp.async, 2 CTAs/SM.
// Load mapping: u-th quarter -> rows (tid>>3)+32u, 16B chunk tid&7.
//   so(u) = swz128(row*128 + c16*16) + u*4096  (32|row-step keeps swizzle)
//   gsrc(u) = base + row*2048 + c16*16 + u*65536
// ---------------------------------------------------------------------------
struct GemmCore {
    uint32_t sb;
    int lane, wm, wn;
    uint32_t so;
    const char *gA, *gB;

    __device__ __forceinline__ void init(uint32_t sb_, int tid,
                                         const char* pA, const char* pB) {
        sb = sb_;
        const int wid = tid >> 5;
        lane = tid & 31;
        wm = wid & 1; wn = wid >> 1;
        const int row = tid >> 3;
        const int c16 = tid & 7;
        so = swz128((uint32_t)(row * 128 + c16 * 16));
        gA = pA + (size_t)row * 2048 + c16 * 16;
        gB = pB + (size_t)row * 2048 + c16 * 16;
    }
    __device__ __forceinline__ void load_stage(int s) {
        const uint32_t st = sb + s * STAGE_B + so;
#pragma unroll
        for (int u = 0; u < 4; ++u) cp16(st + u * 4096, gA + u * 65536);
#pragma unroll
        for (int u = 0; u < 4; ++u) cp16(st + A_TILE_B + u * 4096, gB + u * 65536);
        asm volatile("cp.async.commit_group;" ::: "memory");
        gA += 128; gB += 128;
    }
    __device__ __forceinline__ void load_frags(uint32_t a[4][4], uint32_t b[2][4],
                                               uint32_t tA, uint32_t tB, int kk) {
#pragma unroll
        for (int mt = 0; mt < 4; mt++)
            ldsm4(a[mt], ldsm_addr(tA, wm * 64 + mt * 16, kk, lane));
#pragma unroll
        for (int p = 0; p < 2; p++)
            ldsm4(b[p], ldsm_addr(tB, wn * 32 + p * 16, kk, lane));
    }
    __device__ __forceinline__ void mainloop(float acc[4][4][4]) {
        load_stage(0);
        uint32_t a[2][4][4], b[2][2][4];
        for (int i = 0; i < NCHUNK; ++i) {
            if (i + 1 < NCHUNK) {
                load_stage((i + 1) & 1);
                asm volatile("cp.async.wait_group 1;" ::: "memory");
            } else {
                asm volatile("cp.async.wait_group 0;" ::: "memory");
            }
            __syncthreads();
            const uint32_t st = sb + (i & 1) * STAGE_B;
            const uint32_t tA = st;
            const uint32_t tB = st + A_TILE_B;

            load_frags(a[0], b[0], tA, tB, 0);
#pragma unroll
            for (int kk = 0; kk < 4; ++kk) {
                const int cur = kk & 1;
                if (kk < 3)
                    load_frags(a[cur ^ 1], b[cur ^ 1], tA, tB, kk + 1);
#pragma unroll
                for (int mt = 0; mt < 4; mt++)
#pragma unroll
                    for (int nt = 0; nt < 4; nt++)
                        mma16816(acc[mt][nt], a[cur][mt],
                                 b[cur][nt >> 1][nt & 1],
                                 b[cur][nt >> 1][(nt & 1) + 2]);
            }
            __syncthreads();
        }
    }
};

// ---------------------------------------------------------------------------
// Fused QKV GEMM: W = [Wq;Wk;Wv] (3072x1024), seg = bn>>10.
// ---------------------------------------------------------------------------
__global__ __launch_bounds__(256, 2)
void gemm_qkv(const __half* __restrict__ A,
              const __half* __restrict__ W,
              const float* __restrict__ bq, const float* __restrict__ bk,
              const float* __restrict__ bv,
              __half* __restrict__ q, __half* __restrict__ k,
              __half* __restrict__ v)
{
    extern __shared__ char smem[];
    const int bn = blockIdx.x * 128;
    const int bm = blockIdx.y * 128;
    const int seg = bn >> 10;
    const int ncol = bn & 1023;

    const float* bias = (seg == 0) ? bq : (seg == 1) ? bk : bv;
    __half* out       = (seg == 0) ? q  : (seg == 1) ? k  : v;

    GemmCore core;
    core.init(smem_u32(smem), threadIdx.x,
              (const char*)A + (size_t)bm * 2048,
              (const char*)W + (size_t)bn * 2048);

    float acc[4][4][4];
#pragma unroll
    for (int mt = 0; mt < 4; mt++)
#pragma unroll
        for (int nt = 0; nt < 4; nt++)
#pragma unroll
            for (int r = 0; r < 4; r++) acc[mt][nt][r] = 0.0f;

    core.mainloop(acc);

    const int g = core.lane >> 2;
    const int t = core.lane & 3;
#pragma unroll
    for (int nt = 0; nt < 4; nt++) {
        const int col = ncol + core.wn * 32 + nt * 8 + 2 * t;
        const float b0 = bias[col], b1 = bias[col + 1];
#pragma unroll
        for (int mt = 0; mt < 4; mt++) {
            const int row0 = bm + core.wm * 64 + mt * 16 + g;
            store2(out + (size_t)row0 * C_EMBD + col,
                   acc[mt][nt][0] + b0, acc[mt][nt][1] + b1);
            store2(out + (size_t)(row0 + 8) * C_EMBD + col,
                   acc[mt][nt][2] + b0, acc[mt][nt][3] + b1);
        }
    }
}

// ---------------------------------------------------------------------------
__global__ __launch_bounds__(256, 2)
void gemm_out(const __half* __restrict__ A,
              const __half* __restrict__ W,
              const float* __restrict__ bias,
              float* __restrict__ Cout)
{
    extern __shared__ char smem[];
    const int bn = blockIdx.x * 128;
    const int bm = blockIdx.y * 128;

    GemmCore core;
    core.init(smem_u32(smem), threadIdx.x,
              (const char*)A + (size_t)bm * 2048,
              (const char*)W + (size_t)bn * 2048);

    float acc[4][4][4];
#pragma unroll
    for (int mt = 0; mt < 4; mt++)
#pragma unroll
        for (int nt = 0; nt < 4; nt++)
#pragma unroll
            for (int r = 0; r < 4; r++) acc[mt][nt][r] = 0.0f;

    core.mainloop(acc);

    const int g = core.lane >> 2;
    const int t = core.lane & 3;
#pragma unroll
    for (int nt = 0; nt < 4; nt++) {
        const int col = bn + core.wn * 32 + nt * 8 + 2 * t;
        const float b0 = bias[col], b1 = bias[col + 1];
#pragma unroll
        for (int mt = 0; mt < 4; mt++) {
            const int row0 = bm + core.wm * 64 + mt * 16 + g;
            store2(Cout + (size_t)row0 * C_EMBD + col,
                   acc[mt][nt][0] + b0, acc[mt][nt][1] + b1);
            store2(Cout + (size_t)(row0 + 8) * C_EMBD + col,
                   acc[mt][nt][2] + b0, acc[mt][nt][3] + b1);
        }
    }
}

// ---------------------------------------------------------------------------
// One conversion kernel: x (xn4 float4) then 4 weight matrices (wn4 each).
// ---------------------------------------------------------------------------
__global__ __launch_bounds__(256)
void conv_all(const float* __restrict__ x, __half* __restrict__ xh, int xn4,
              const float* __restrict__ w0, const float* __restrict__ w1,
              const float* __restrict__ w2, const float* __restrict__ w3,
              __half* __restrict__ wout, int wn4)
{
    int i = blockIdx.x * 256 + threadIdx.x;
    const float* src;
    __half* dst;
    int idx;
    if (i < xn4) {
        src = x; dst = xh; idx = i;
    } else {
        int j = i - xn4;
        int which = j / wn4;
        if (which >= 4) return;
        idx = j - which * wn4;
        src = (which == 0) ? w0 : (which == 1) ? w1 : (which == 2) ? w2 : w3;
        dst = wout + (size_t)which * (size_t)wn4 * 4;
    }
    float4 val = ((const float4*)src)[idx];
    __half h[4] = {__float2half(val.x), __float2half(val.y),
                   __float2half(val.z), __float2half(val.w)};
    ((ushort4*)dst)[idx] = *(ushort4*)h;
}

// ---------------------------------------------------------------------------
// Banded trigram attention, thread-per-(row,head).
// 128 thr = 8 rows x 16 heads. SMEM: k[10], v[10] only (q has a single
// consumer -> read straight from global in the same rotated pattern).
// ---------------------------------------------------------------------------
__global__ __launch_bounds__(128, 4)
void trigram_attn(const __half* __restrict__ q, const __half* __restrict__ k,
                  const __half* __restrict__ v, __half* __restrict__ y)
{
    extern __shared__ __half sm[];
    __half* smk = sm;                       // 10 * 1024
    __half* smv = sm + 10 * C_EMBD;         // 10 * 1024

    const int tid = threadIdx.x;
    const int r0  = blockIdx.x * AT_ROWS;

    // stage k, v: 10 rows * 128 uint4 = 1280 uint4 each (rows r0-2..r0+7)
    {
        const uint4* ks = (const uint4*)k;
        const uint4* vs = (const uint4*)v;
        uint4* kd = (uint4*)smk;
        uint4* vd = (uint4*)smv;
#pragma unroll
        for (int u = 0; u < 10; u++) {
            int idx = tid + 128 * u;           // 0..1279
            int rr  = idx >> 7;                // 0..9
            int cc  = idx & 127;
            int gr  = r0 - 2 + rr; if (gr < 0) gr = 0;
            kd[idx] = ks[(size_t)gr * 128 + cc];
            vd[idx] = vs[(size_t)gr * 128 + cc];
        }
    }
    __syncthreads();

    const int lr = tid >> 4;                  // 0..7
    const int h  = tid & 15;
    const int t  = (r0 & (T_LEN - 1)) + lr;

    const uint4* qrow = (const uint4*)q + ((size_t)(r0 + lr) * 128 + h * 8);
    const uint4* k0   = (const uint4*)(smk + (lr + 2) * C_EMBD + h * 64);
    const uint4* k1   = (const uint4*)(smk + (lr + 1) * C_EMBD + h * 64);
    const uint4* k2   = (const uint4*)(smk + (lr + 0) * C_EMBD + h * 64);

    float p0a = 0, p0b = 0, p1a = 0, p1b = 0, p2a = 0, p2b = 0;
#pragma unroll
    for (int i = 0; i < 8; i++) {
        const int c = (i + h) & 7;
        const uint4 qc = qrow[c];
        dot8(p0a, p0b, qc, k0[c]);
        dot8(p1a, p1b, qc, k1[c]);
        dot8(p2a, p2b, qc, k2[c]);
    }
    float s0 = (p0a + p0b) * 0.125f;
    float s1 = (p1a + p1b) * 0.125f;
    float s2 = (p2a + p2b) * 0.125f;

    float m = s0;
    if (t >= 1 && s1 > m) m = s1;
    if (t >= 2 && s2 > m) m = s2;
    float e0 = expf(s0 - m);
    float e1 = (t >= 1) ? expf(s1 - m) : 0.0f;
    float e2 = (t >= 2) ? expf(s2 - m) : 0.0f;
    const float inv = 1.0f / (e0 + e1 + e2);
    const float a0 = e0 * inv, a1 = e1 * inv, a2 = e2 * inv;

    const uint4* v0 = (const uint4*)(smv + (lr + 2) * C_EMBD + h * 64);
    const uint4* v1 = (const uint4*)(smv + (lr + 1) * C_EMBD + h * 64);
    const uint4* v2 = (const uint4*)(smv + (lr + 0) * C_EMBD + h * 64);
    uint4* yout = (uint4*)(y + (size_t)(r0 + lr) * C_EMBD + h * 64);

#pragma unroll
    for (int i = 0; i < 8; i++) {
        const int c = (i + h) & 7;
        const uint4 w0 = v0[c], w1 = v1[c], w2 = v2[c];
        const __half2* h0 = (const __half2*)&w0;
        const __half2* h1 = (const __half2*)&w1;
        const __half2* h2 = (const __half2*)&w2;
        uint4 o;
        __half2* oh = (__half2*)&o;
#pragma unroll
        for (int e = 0; e < 4; e++) {
            float2 f0 = __half22float2(h0[e]);
            float2 f1 = __half22float2(h1[e]);
            float2 f2 = __half22float2(h2[e]);
            float yx = a0 * f0.x + a1 * f1.x + a2 * f2.x;
            float yy = a0 * f0.y + a1 * f1.y + a2 * f2.y;
            oh[e] = __floats2half2_rn(yx, yy);
        }
        yout[c] = o;
    }
}

// ---------------------------------------------------------------------------
extern "C" void kernel_launch(void* const* d_in, const int* in_sizes, int n_in,
                              void* d_out, int out_size)
{
    const float* x  = (const float*)d_in[0];
    const float* W[4]    = {(const float*)d_in[1], (const float*)d_in[3],
                            (const float*)d_in[5], (const float*)d_in[7]};
    const float* bias[4] = {(const float*)d_in[2], (const float*)d_in[4],
                            (const float*)d_in[6], (const float*)d_in[8]};
    float* out = (float*)d_out;

    const int rows = in_sizes[0] / C_EMBD;   // 32768

    __half *xh, *yh, *w, *q, *k, *v;
    cudaGetSymbolAddress((void**)&xh, g_xh);
    cudaGetSymbolAddress((void**)&yh, g_yh);
    cudaGetSymbolAddress((void**)&w,  g_w);
    cudaGetSymbolAddress((void**)&q,  g_q);
    cudaGetSymbolAddress((void**)&k,  g_k);
    cudaGetSymbolAddress((void**)&v,  g_v);

    cudaFuncSetAttribute(gemm_qkv,
                         cudaFuncAttributeMaxDynamicSharedMemorySize, GEMM_SMEM);
    cudaFuncSetAttribute(gemm_out,
                         cudaFuncAttributeMaxDynamicSharedMemorySize, GEMM_SMEM);
    cudaFuncSetAttribute(trigram_attn,
                         cudaFuncAttributeMaxDynamicSharedMemorySize, AT_SMEM);

    const int xn4 = rows * C_EMBD / 4;
    const int wn4 = C_EMBD * C_EMBD / 4;
    conv_all<<<(xn4 + 4 * wn4 + 255) / 256, 256>>>(x, xh, xn4,
                                                   W[0], W[1], W[2], W[3],
                                                   w, wn4);

    const size_t WSZ = (size_t)C_EMBD * C_EMBD;

    dim3 gqkv(3 * C_EMBD / 128, rows / 128);
    gemm_qkv<<<gqkv, 256, GEMM_SMEM>>>(xh, w, bias[0], bias[1], bias[2],
                                       q, k, v);

    trigram_attn<<<rows / AT_ROWS, 128, AT_SMEM>>>(q, k, v, yh);

    dim3 gout(C_EMBD / 128, rows / 128);
    gemm_out<<<gout, 256, GEMM_SMEM>>>(yh, w + 3 * WSZ, bias[3], out);
}